// round 15
// baseline (speedup 1.0000x reference)
#include <cuda_runtime.h>
#include <float.h>
#include <math.h>

#define NB 4
#define CC 96
#define NN 3136
#define KNN 9
#define CMM 192
#define HH 56

// ---------------- scratch (device globals: allocation-free) ----------------
__device__ __align__(16) float g_h[NB * CC * NN];                 // fc1 output [b][c][n]
__device__ __align__(16) float g_x2[NB * NN];                     // sum h^2 per node
__device__ __align__(16) float g_D[(size_t)NB * NN * NN];         // reduced dist (157MB)
__device__ __align__(16) int   g_idx[NB * NN * KNN];              // knn indices
__device__ __align__(16) float g_wt[CC * 384];                    // combined uv weight [c][r]
__device__ __align__(16) float g_ub[384];                         // combined uv bias
__device__ __align__(16) float g_uv[(size_t)NB * NN * 384];       // [b][n][0..191]=u,[192..383]=v
__device__ __align__(16) float g_g[(size_t)NB * NN * CMM];        // gathered features [node][192]
__device__ __align__(16) float g_out[NB * CC * NN];               // pre-attention out [b][o][n]
__device__ __align__(16) float g_avg[NB * NN];
__device__ __align__(16) float g_mx[NB * NN];

// ---------------- K1: fc1 (h = W x + b) and x2 ----------------
__global__ void k_fc1(const float* __restrict__ x, const float* __restrict__ w,
                      const float* __restrict__ bias) {
    __shared__ __align__(16) float Xs[96][64];
    __shared__ float Ws[32][96];
    __shared__ float S2[256];
    int b = blockIdx.y;
    int n0 = blockIdx.x * 64;
    int tid = threadIdx.x;

    for (int i = tid; i < 96 * 64; i += 256) {
        int c = i >> 6, j = i & 63;
        Xs[c][j] = x[((b * 96) + c) * NN + n0 + j];
    }
    int oz = tid >> 6;
    int j  = tid & 63;
    float s2 = 0.f;

    for (int oc = 0; oc < 3; oc++) {
        __syncthreads();
        for (int i = tid; i < 32 * 96; i += 256) {
            int oo = i / 96, c = i % 96;
            Ws[oo][c] = w[(oc * 32 + oo) * 96 + c];
        }
        __syncthreads();
        float acc[8];
#pragma unroll
        for (int q = 0; q < 8; q++) acc[q] = bias[oc * 32 + oz * 8 + q];
        for (int c = 0; c < 96; c++) {
            float xc = Xs[c][j];
#pragma unroll
            for (int q = 0; q < 8; q++) acc[q] += Ws[oz * 8 + q][c] * xc;
        }
#pragma unroll
        for (int q = 0; q < 8; q++) {
            int o = oc * 32 + oz * 8 + q;
            g_h[((b * 96) + o) * NN + n0 + j] = acc[q];
            s2 += acc[q] * acc[q];
        }
    }
    S2[tid] = s2;
    __syncthreads();
    if (oz == 0) {
        float t = S2[j] + S2[64 + j] + S2[128 + j] + S2[192 + j];
        g_x2[b * NN + n0 + j] = t;
    }
}

// ---------------- K1b: combined uv weights (transposed) + bias ----------------
__global__ void k_prep(const float* __restrict__ gw, const float* __restrict__ gb) {
    int i = blockIdx.x * 256 + threadIdx.x;
    if (i < 96 * 384) {
        int c = i / 384, r = i % 384;
        float wv = (r < 192) ? gw[r * 192 + c] - gw[r * 192 + 96 + c]
                             : gw[(r - 192) * 192 + 96 + c];
        g_wt[c * 384 + r] = wv;
    }
    if (i < 384) g_ub[i] = (i < 192) ? gb[i] : 0.f;
}

// ---------------- K2: FUSED gemm kernel: dist (p<325) + uv (p>=325) ----------------
__global__ void __launch_bounds__(256, 2) k_gemm() {
    __shared__ __align__(16) float smem_buf[8192];
    float (*As)[16][128] = (float(*)[16][128])smem_buf;
    float (*Bs)[16][128] = (float(*)[16][128])(smem_buf + 4096);

    int p = blockIdx.x;
    int b = blockIdx.y;
    int tid = threadIdx.x, tx = tid & 15, ty = tid >> 4;

    int s0 = tid, s1 = tid + 256;
    int k0 = s0 >> 5, m0 = (s0 & 31) * 4;
    int k1 = s1 >> 5, m1 = (s1 & 31) * 4;

    float4 pa0, pa1, pb0, pb1;
    const float4 z4 = make_float4(0.f, 0.f, 0.f, 0.f);

    if (p < 325) {
        int bj = (int)((sqrtf(8.0f * (float)p + 1.0f) - 1.0f) * 0.5f);
        while ((bj + 1) * (bj + 2) / 2 <= p) bj++;
        while (bj * (bj + 1) / 2 > p) bj--;
        int bi = p - bj * (bj + 1) / 2;

        int ni0 = bi * 128, nj0 = bj * 128;
        const float* hb = g_h + (size_t)b * 96 * NN;
        float* Db = g_D + (size_t)b * NN * NN;

#define LDG_TILE(kc)                                                                        \
        {                                                                                   \
            int c0 = (kc) * 16 + k0, c1 = (kc) * 16 + k1;                                   \
            pa0 = (ni0 + m0 < NN) ? *(const float4*)(hb + (size_t)c0 * NN + ni0 + m0) : z4; \
            pa1 = (ni0 + m1 < NN) ? *(const float4*)(hb + (size_t)c1 * NN + ni0 + m1) : z4; \
            pb0 = (nj0 + m0 < NN) ? *(const float4*)(hb + (size_t)c0 * NN + nj0 + m0) : z4; \
            pb1 = (nj0 + m1 < NN) ? *(const float4*)(hb + (size_t)c1 * NN + nj0 + m1) : z4; \
        }
#define STS_TILE(buf)                                                                       \
        {                                                                                   \
            *(float4*)&As[buf][k0][m0] = pa0; *(float4*)&As[buf][k1][m1] = pa1;             \
            *(float4*)&Bs[buf][k0][m0] = pb0; *(float4*)&Bs[buf][k1][m1] = pb1;             \
        }

        float acc[8][8];
#pragma unroll
        for (int i = 0; i < 8; i++)
#pragma unroll
            for (int j = 0; j < 8; j++) acc[i][j] = 0.f;

        LDG_TILE(0);
        STS_TILE(0);

        for (int kc = 0; kc < 6; kc++) {
            __syncthreads();
            if (kc < 5) LDG_TILE(kc + 1);
            int buf = kc & 1;
#pragma unroll
            for (int k = 0; k < 16; k++) {
                float4 a0 = *(const float4*)&As[buf][k][ty * 4];
                float4 a1 = *(const float4*)&As[buf][k][64 + ty * 4];
                float4 b0 = *(const float4*)&Bs[buf][k][tx * 4];
                float4 b1 = *(const float4*)&Bs[buf][k][64 + tx * 4];
                float ar[8] = {a0.x, a0.y, a0.z, a0.w, a1.x, a1.y, a1.z, a1.w};
                float br[8] = {b0.x, b0.y, b0.z, b0.w, b1.x, b1.y, b1.z, b1.w};
#pragma unroll
                for (int i = 0; i < 8; i++)
#pragma unroll
                    for (int j = 0; j < 8; j++) acc[i][j] += ar[i] * br[j];
            }
            if (kc < 5) STS_TILE((kc + 1) & 1);
        }
#undef LDG_TILE
#undef STS_TILE

        float x2i[8], x2j[8];
#pragma unroll
        for (int g = 0; g < 2; g++)
#pragma unroll
            for (int q = 0; q < 4; q++) {
                int ni = ni0 + g * 64 + ty * 4 + q;
                int nj = nj0 + g * 64 + tx * 4 + q;
                x2i[g * 4 + q] = (ni < NN) ? g_x2[b * NN + ni] : 0.f;
                x2j[g * 4 + q] = (nj < NN) ? g_x2[b * NN + nj] : 0.f;
            }

#pragma unroll
        for (int rg = 0; rg < 2; rg++)
#pragma unroll
            for (int r = 0; r < 4; r++) {
                int ni = ni0 + rg * 64 + ty * 4 + r;
                if (ni < NN) {
                    int ri = rg * 4 + r;
#pragma unroll
                    for (int cg = 0; cg < 2; cg++) {
                        int cb = nj0 + cg * 64 + tx * 4;
                        if (cb < NN) {
                            float4 v;
                            v.x = x2j[cg * 4 + 0] - 2.f * acc[ri][cg * 4 + 0];
                            v.y = x2j[cg * 4 + 1] - 2.f * acc[ri][cg * 4 + 1];
                            v.z = x2j[cg * 4 + 2] - 2.f * acc[ri][cg * 4 + 2];
                            v.w = x2j[cg * 4 + 3] - 2.f * acc[ri][cg * 4 + 3];
                            *(float4*)&Db[(size_t)ni * NN + cb] = v;
                        }
                    }
                }
            }

        if (bi < bj) {
#pragma unroll
            for (int cg = 0; cg < 2; cg++)
#pragma unroll
                for (int jj = 0; jj < 4; jj++) {
                    int nj = nj0 + cg * 64 + tx * 4 + jj;
                    if (nj < NN) {
                        int ci = cg * 4 + jj;
#pragma unroll
                        for (int rg = 0; rg < 2; rg++) {
                            int rb = ni0 + rg * 64 + ty * 4;
                            if (rb < NN) {
                                float4 v;
                                v.x = x2i[rg * 4 + 0] - 2.f * acc[rg * 4 + 0][ci];
                                v.y = x2i[rg * 4 + 1] - 2.f * acc[rg * 4 + 1][ci];
                                v.z = x2i[rg * 4 + 2] - 2.f * acc[rg * 4 + 2][ci];
                                v.w = x2i[rg * 4 + 3] - 2.f * acc[rg * 4 + 3][ci];
                                *(float4*)&Db[(size_t)nj * NN + rb] = v;
                            }
                        }
                    }
                }
        }
    } else {
        int q = p - 325;
        int bn = q % 25;
        int br = q / 25;
        int r0 = br * 128, n0 = bn * 128;
        const float* hb = g_h + (size_t)b * 96 * NN;

#define LDG_TILE(kc)                                                                        \
        {                                                                                   \
            int c0 = (kc) * 16 + k0, c1 = (kc) * 16 + k1;                                   \
            pa0 = *(const float4*)(g_wt + c0 * 384 + r0 + m0);                              \
            pa1 = *(const float4*)(g_wt + c1 * 384 + r0 + m1);                              \
            pb0 = (n0 + m0 < NN) ? *(const float4*)(hb + (size_t)c0 * NN + n0 + m0) : z4;   \
            pb1 = (n0 + m1 < NN) ? *(const float4*)(hb + (size_t)c1 * NN + n0 + m1) : z4;   \
        }
#define STS_TILE(buf)                                                                       \
        {                                                                                   \
            *(float4*)&As[buf][k0][m0] = pa0; *(float4*)&As[buf][k1][m1] = pa1;             \
            *(float4*)&Bs[buf][k0][m0] = pb0; *(float4*)&Bs[buf][k1][m1] = pb1;             \
        }

        float acc[8][8];
#pragma unroll
        for (int i = 0; i < 8; i++)
#pragma unroll
            for (int j = 0; j < 8; j++) acc[i][j] = 0.f;

        LDG_TILE(0);
        STS_TILE(0);

        for (int kc = 0; kc < 6; kc++) {
            __syncthreads();
            if (kc < 5) LDG_TILE(kc + 1);
            int buf = kc & 1;
#pragma unroll
            for (int k = 0; k < 16; k++) {
                float4 a0 = *(const float4*)&As[buf][k][ty * 4];
                float4 a1 = *(const float4*)&As[buf][k][64 + ty * 4];
                float4 b0 = *(const float4*)&Bs[buf][k][tx * 4];
                float4 b1 = *(const float4*)&Bs[buf][k][64 + tx * 4];
                float ar[8] = {a0.x, a0.y, a0.z, a0.w, a1.x, a1.y, a1.z, a1.w};
                float br2[8] = {b0.x, b0.y, b0.z, b0.w, b1.x, b1.y, b1.z, b1.w};
#pragma unroll
                for (int i = 0; i < 8; i++)
#pragma unroll
                    for (int j = 0; j < 8; j++) acc[i][j] += ar[i] * br2[j];
            }
            if (kc < 5) STS_TILE((kc + 1) & 1);
        }
#undef LDG_TILE
#undef STS_TILE

        float bv[8];
#pragma unroll
        for (int rg = 0; rg < 2; rg++)
#pragma unroll
            for (int r = 0; r < 4; r++) bv[rg * 4 + r] = g_ub[r0 + rg * 64 + ty * 4 + r];

#pragma unroll
        for (int cg = 0; cg < 2; cg++)
#pragma unroll
            for (int jj = 0; jj < 4; jj++) {
                int n = n0 + cg * 64 + tx * 4 + jj;
                if (n < NN) {
                    int ci = cg * 4 + jj;
                    float* dst = g_uv + ((size_t)(b * NN) + n) * 384 + r0;
#pragma unroll
                    for (int rg = 0; rg < 2; rg++) {
                        float4 v;
                        v.x = acc[rg * 4 + 0][ci] + bv[rg * 4 + 0];
                        v.y = acc[rg * 4 + 1][ci] + bv[rg * 4 + 1];
                        v.z = acc[rg * 4 + 2][ci] + bv[rg * 4 + 2];
                        v.w = acc[rg * 4 + 3][ci] + bv[rg * 4 + 3];
                        *(float4*)(dst + rg * 64 + ty * 4) = v;
                    }
                }
            }
    }
}

// ---------------- K3: top-9, 16-wide gated warp queue (MLP=4) ----------------
__device__ __forceinline__ unsigned long long pack_key(float d, int id) {
    unsigned u = __float_as_uint(d);
    u ^= (u & 0x80000000u) ? 0xFFFFFFFFu : 0x80000000u;  // sortable-float map
    return ((unsigned long long)u << 32) | (unsigned)id;
}

__device__ __forceinline__ float key_to_dist(unsigned long long k) {
    unsigned u = (unsigned)(k >> 32);
    u ^= (u & 0x80000000u) ? 0x80000000u : 0xFFFFFFFFu;  // inverse map
    return __uint_as_float(u);
}

__global__ void k_topk() {
    const unsigned FULL = 0xffffffffu;
    const unsigned long long KMAX = 0xFFFFFFFFFFFFFFFFull;
    int warp = threadIdx.x >> 5;
    int lane = threadIdx.x & 31;
    int row = blockIdx.x * 8 + warp;  // b*NN + n
    const float4* Drow = (const float4*)(g_D + (size_t)row * NN);

    unsigned long long q9 = KMAX;   // lanes 0..8: sorted top-9 ascending
    unsigned long long wth = KMAX;  // q9 @ lane 8 (warp-uniform)
    float wth_f = FLT_MAX;          // distance at threshold (warp-uniform, conservative)

    const float4 m4 = make_float4(FLT_MAX, FLT_MAX, FLT_MAX, FLT_MAX);

    for (int it = 0; it < 7; it++) {    // 7*128 = 896 >= 784 float4 slots
        int sA = it * 128 + lane;
        int sB = sA + 32;
        int sC = sA + 64;
        int sD = sA + 96;
        // 4 independent loads issued before any use (MLP=4)
        float4 a = (sA < 784) ? __ldcs(&Drow[sA]) : m4;
        float4 c = (sB < 784) ? __ldcs(&Drow[sB]) : m4;
        float4 e = (sC < 784) ? __ldcs(&Drow[sC]) : m4;
        float4 f = (sD < 784) ? __ldcs(&Drow[sD]) : m4;

        // lane-local min of 16 (no warp ops)
        float mn = fminf(
            fminf(fminf(fminf(a.x, a.y), fminf(a.z, a.w)),
                  fminf(fminf(c.x, c.y), fminf(c.z, c.w))),
            fminf(fminf(fminf(e.x, e.y), fminf(e.z, e.w)),
                  fminf(fminf(f.x, f.y), fminf(f.z, f.w))));
        unsigned g = __ballot_sync(FULL, mn <= wth_f);
        if (!g) continue;

        float dv[16] = {a.x, a.y, a.z, a.w, c.x, c.y, c.z, c.w,
                        e.x, e.y, e.z, e.w, f.x, f.y, f.z, f.w};
        int   iv[16] = {sA * 4, sA * 4 + 1, sA * 4 + 2, sA * 4 + 3,
                        sB * 4, sB * 4 + 1, sB * 4 + 2, sB * 4 + 3,
                        sC * 4, sC * 4 + 1, sC * 4 + 2, sC * 4 + 3,
                        sD * 4, sD * 4 + 1, sD * 4 + 2, sD * 4 + 3};
#pragma unroll
        for (int qq = 0; qq < 16; qq++) {
            float d = dv[qq];
            unsigned long long k = (d <= wth_f) ? pack_key(d, iv[qq]) : KMAX;
            for (int r = 0; r < 32; r++) {
                unsigned m = __ballot_sync(FULL, k < wth);
                if (!m) break;
                int src = __ffs(m) - 1;
                unsigned long long bk = __shfl_sync(FULL, k, src);
                unsigned long long prev = __shfl_up_sync(FULL, q9, 1);
                if (lane == 0) prev = 0ull;
                q9 = (bk >= q9) ? q9 : (prev > bk ? prev : bk);
                wth = __shfl_sync(FULL, q9, 8);
                wth_f = key_to_dist(wth);
                if (lane == src) k = KMAX;
            }
        }
    }
    if (lane < 9) g_idx[row * 9 + lane] = (int)(q9 & 0xFFFFFFFFull);
}

// ---------------- K5a: gather + maxpool + relu -> g_g[node][192] ----------------
__global__ void k_gather() {
    int tid = threadIdx.x;
    int warp = tid >> 5, lane = tid & 31;
    int node = blockIdx.x * 8 + warp;
    int b = node / NN, n = node % NN;
    const float* uvb = g_uv + (size_t)b * NN * 384;

    int nb[9];
#pragma unroll
    for (int k = 0; k < 9; k++) nb[k] = g_idx[node * 9 + k];

#pragma unroll
    for (int s = 0; s < 6; s++) {
        int c = lane + 32 * s;
        float u = uvb[(size_t)n * 384 + c];
        float m = -FLT_MAX;
#pragma unroll
        for (int k = 0; k < 9; k++)
            m = fmaxf(m, uvb[(size_t)nb[k] * 384 + 192 + c]);
        g_g[(size_t)node * 192 + c] = fmaxf(u + m, 0.f);
    }
}

// ---------------- K5b: fc2 GEMM 96x64 tiles + avg/max epilogue ----------------
__global__ void __launch_bounds__(256) k_fc2(const float* __restrict__ fw,
                                             const float* __restrict__ fb) {
    __shared__ float Ws[32][97];
    __shared__ float gs[32][68];
    __shared__ float red_s[16][68];
    __shared__ float red_m[16][68];

    int tid = threadIdx.x;
    int tx = tid & 15, ty = tid >> 4;
    int bn = blockIdx.x;
    int b  = blockIdx.y;
    int n0 = bn * 64;
    const float* gbase = g_g + ((size_t)b * NN + n0) * 192;

    float acc[6][4] = {};

    for (int kc = 0; kc < 6; kc++) {
        __syncthreads();
        for (int i = tid; i < 96 * 32; i += 256) {
            int o = i >> 5, cl = i & 31;
            Ws[cl][o] = fw[o * 192 + kc * 32 + cl];
        }
        for (int i = tid; i < 512; i += 256) {
            int n = i >> 3, cq = i & 7;
            float4 v = *(const float4*)(gbase + (size_t)n * 192 + kc * 32 + cq * 4);
            gs[cq * 4 + 0][n] = v.x;
            gs[cq * 4 + 1][n] = v.y;
            gs[cq * 4 + 2][n] = v.z;
            gs[cq * 4 + 3][n] = v.w;
        }
        __syncthreads();
#pragma unroll
        for (int k = 0; k < 32; k++) {
            float4 gv = *(const float4*)&gs[k][tx * 4];
            float gr[4] = {gv.x, gv.y, gv.z, gv.w};
#pragma unroll
            for (int q = 0; q < 6; q++) {
                float wv = Ws[k][ty * 6 + q];
#pragma unroll
                for (int p = 0; p < 4; p++) acc[q][p] += wv * gr[p];
            }
        }
    }

    float psum[4] = {0.f, 0.f, 0.f, 0.f};
    float pmax[4] = {-FLT_MAX, -FLT_MAX, -FLT_MAX, -FLT_MAX};
#pragma unroll
    for (int q = 0; q < 6; q++) {
        int o = ty * 6 + q;
        float bias = fb[o];
        float4 v;
        float vv[4];
#pragma unroll
        for (int p = 0; p < 4; p++) {
            vv[p] = acc[q][p] + bias;
            psum[p] += vv[p];
            pmax[p] = fmaxf(pmax[p], vv[p]);
        }
        v.x = vv[0]; v.y = vv[1]; v.z = vv[2]; v.w = vv[3];
        *(float4*)&g_out[((size_t)(b * 96 + o)) * NN + n0 + tx * 4] = v;
    }
    __syncthreads();
#pragma unroll
    for (int p = 0; p < 4; p++) {
        red_s[ty][tx * 4 + p] = psum[p];
        red_m[ty][tx * 4 + p] = pmax[p];
    }
    __syncthreads();
#pragma unroll
    for (int off = 8; off > 0; off >>= 1) {
        if (ty < off) {
#pragma unroll
            for (int p = 0; p < 4; p++) {
                red_s[ty][tx * 4 + p] += red_s[ty + off][tx * 4 + p];
                red_m[ty][tx * 4 + p] = fmaxf(red_m[ty][tx * 4 + p], red_m[ty + off][tx * 4 + p]);
            }
        }
        __syncthreads();
    }
    if (ty == 0) {
#pragma unroll
        for (int p = 0; p < 4; p++) {
            g_avg[b * NN + n0 + tx * 4 + p] = red_s[0][tx * 4 + p] * (1.f / 96.f);
            g_mx[b * NN + n0 + tx * 4 + p]  = red_m[0][tx * 4 + p];
        }
    }
}

// ---------------- K6: 7x7 spatial attention + sigmoid + residual ----------------
__global__ void k_att(const float* __restrict__ sw_g, const float* __restrict__ x,
                      float* __restrict__ out) {
    __shared__ float sw[98];
    int tid = threadIdx.x;
    if (tid < 98) sw[tid] = sw_g[tid];
    __syncthreads();
    int b = blockIdx.y;
    int n = blockIdx.x * 256 + tid;
    if (n >= NN) return;
    int y = n / HH, x0 = n % HH;
    const float* avgb = g_avg + b * NN;
    const float* mxb  = g_mx + b * NN;
    float acc = 0.f;
#pragma unroll
    for (int dy = 0; dy < 7; dy++) {
        int yy = y + dy - 3;
        if ((unsigned)yy < HH) {
#pragma unroll
            for (int dx = 0; dx < 7; dx++) {
                int xx = x0 + dx - 3;
                if ((unsigned)xx < HH) {
                    int nn = yy * HH + xx;
                    acc += sw[dy * 7 + dx] * avgb[nn] + sw[49 + dy * 7 + dx] * mxb[nn];
                }
            }
        }
    }
    float att = 1.f / (1.f + expf(-acc));
    for (int o = 0; o < 96; o++) {
        size_t off = ((size_t)(b * 96 + o)) * NN + n;
        out[off] = g_out[off] * att + x[off];
    }
}

// ---------------- launch ----------------
extern "C" void kernel_launch(void* const* d_in, const int* in_sizes, int n_in,
                              void* d_out, int out_size) {
    const float* x       = (const float*)d_in[0];
    const float* fc1_w   = (const float*)d_in[1];
    const float* fc1_b   = (const float*)d_in[2];
    const float* gconv_w = (const float*)d_in[3];
    const float* gconv_b = (const float*)d_in[4];
    const float* fc2_w   = (const float*)d_in[5];
    const float* fc2_b   = (const float*)d_in[6];
    const float* sa_w    = (const float*)d_in[7];
    float* out = (float*)d_out;

    k_fc1  <<<dim3(49, 4), 256>>>(x, fc1_w, fc1_b);
    k_prep <<<144, 256>>>(gconv_w, gconv_b);
    k_gemm <<<dim3(400, 4), 256>>>();      // fused dist (325) + uv (75)
    k_topk <<<1568, 256>>>();
    k_gather<<<1568, 256>>>();
    k_fc2  <<<dim3(49, 4), 256>>>(fc2_w, fc2_b);
    k_att  <<<dim3(13, 4), 256>>>(sa_w, x, out);
}

// round 16
// speedup vs baseline: 1.0114x; 1.0114x over previous
#include <cuda_runtime.h>
#include <float.h>
#include <math.h>

#define NB 4
#define CC 96
#define NN 3136
#define KNN 9
#define CMM 192
#define HH 56

// ---------------- scratch (device globals: allocation-free) ----------------
__device__ __align__(16) float g_h[NB * CC * NN];                 // fc1 output [b][c][n]
__device__ __align__(16) float g_x2[NB * NN];                     // sum h^2 per node
__device__ __align__(16) float g_D[(size_t)NB * NN * NN];         // reduced dist (157MB)
__device__ __align__(16) int   g_idx[NB * NN * KNN];              // knn indices
__device__ __align__(16) float g_wt[CC * 384];                    // combined uv weight [c][r]
__device__ __align__(16) float g_ub[384];                         // combined uv bias
__device__ __align__(16) float g_uv[(size_t)NB * NN * 384];       // [b][n][0..191]=u,[192..383]=v
__device__ __align__(16) float g_g[(size_t)NB * NN * CMM];        // gathered features [node][192]
__device__ __align__(16) float g_out[NB * CC * NN];               // pre-attention out [b][o][n]
__device__ __align__(16) float g_avg[NB * NN];
__device__ __align__(16) float g_mx[NB * NN];

// ---------------- K1: fc1 (h = W x + b) and x2 ----------------
__global__ void k_fc1(const float* __restrict__ x, const float* __restrict__ w,
                      const float* __restrict__ bias) {
    __shared__ __align__(16) float Xs[96][64];
    __shared__ float Ws[32][96];
    __shared__ float S2[256];
    int b = blockIdx.y;
    int n0 = blockIdx.x * 64;
    int tid = threadIdx.x;

    for (int i = tid; i < 96 * 64; i += 256) {
        int c = i >> 6, j = i & 63;
        Xs[c][j] = x[((b * 96) + c) * NN + n0 + j];
    }
    int oz = tid >> 6;
    int j  = tid & 63;
    float s2 = 0.f;

    for (int oc = 0; oc < 3; oc++) {
        __syncthreads();
        for (int i = tid; i < 32 * 96; i += 256) {
            int oo = i / 96, c = i % 96;
            Ws[oo][c] = w[(oc * 32 + oo) * 96 + c];
        }
        __syncthreads();
        float acc[8];
#pragma unroll
        for (int q = 0; q < 8; q++) acc[q] = bias[oc * 32 + oz * 8 + q];
        for (int c = 0; c < 96; c++) {
            float xc = Xs[c][j];
#pragma unroll
            for (int q = 0; q < 8; q++) acc[q] += Ws[oz * 8 + q][c] * xc;
        }
#pragma unroll
        for (int q = 0; q < 8; q++) {
            int o = oc * 32 + oz * 8 + q;
            g_h[((b * 96) + o) * NN + n0 + j] = acc[q];
            s2 += acc[q] * acc[q];
        }
    }
    S2[tid] = s2;
    __syncthreads();
    if (oz == 0) {
        float t = S2[j] + S2[64 + j] + S2[128 + j] + S2[192 + j];
        g_x2[b * NN + n0 + j] = t;
    }
}

// ---------------- K1b: combined uv weights (transposed) + bias ----------------
__global__ void k_prep(const float* __restrict__ gw, const float* __restrict__ gb) {
    int i = blockIdx.x * 256 + threadIdx.x;
    if (i < 96 * 384) {
        int c = i / 384, r = i % 384;
        float wv = (r < 192) ? gw[r * 192 + c] - gw[r * 192 + 96 + c]
                             : gw[(r - 192) * 192 + 96 + c];
        g_wt[c * 384 + r] = wv;
    }
    if (i < 384) g_ub[i] = (i < 192) ? gb[i] : 0.f;
}

// ---------------- K2: FUSED gemm kernel: dist (p<325) + uv (p>=325) ----------------
__global__ void __launch_bounds__(256, 2) k_gemm() {
    __shared__ __align__(16) float smem_buf[8192];
    float (*As)[16][128] = (float(*)[16][128])smem_buf;
    float (*Bs)[16][128] = (float(*)[16][128])(smem_buf + 4096);

    int p = blockIdx.x;
    int b = blockIdx.y;
    int tid = threadIdx.x, tx = tid & 15, ty = tid >> 4;

    int s0 = tid, s1 = tid + 256;
    int k0 = s0 >> 5, m0 = (s0 & 31) * 4;
    int k1 = s1 >> 5, m1 = (s1 & 31) * 4;

    float4 pa0, pa1, pb0, pb1;
    const float4 z4 = make_float4(0.f, 0.f, 0.f, 0.f);

    if (p < 325) {
        int bj = (int)((sqrtf(8.0f * (float)p + 1.0f) - 1.0f) * 0.5f);
        while ((bj + 1) * (bj + 2) / 2 <= p) bj++;
        while (bj * (bj + 1) / 2 > p) bj--;
        int bi = p - bj * (bj + 1) / 2;

        int ni0 = bi * 128, nj0 = bj * 128;
        const float* hb = g_h + (size_t)b * 96 * NN;
        float* Db = g_D + (size_t)b * NN * NN;

#define LDG_TILE(kc)                                                                        \
        {                                                                                   \
            int c0 = (kc) * 16 + k0, c1 = (kc) * 16 + k1;                                   \
            pa0 = (ni0 + m0 < NN) ? *(const float4*)(hb + (size_t)c0 * NN + ni0 + m0) : z4; \
            pa1 = (ni0 + m1 < NN) ? *(const float4*)(hb + (size_t)c1 * NN + ni0 + m1) : z4; \
            pb0 = (nj0 + m0 < NN) ? *(const float4*)(hb + (size_t)c0 * NN + nj0 + m0) : z4; \
            pb1 = (nj0 + m1 < NN) ? *(const float4*)(hb + (size_t)c1 * NN + nj0 + m1) : z4; \
        }
#define STS_TILE(buf)                                                                       \
        {                                                                                   \
            *(float4*)&As[buf][k0][m0] = pa0; *(float4*)&As[buf][k1][m1] = pa1;             \
            *(float4*)&Bs[buf][k0][m0] = pb0; *(float4*)&Bs[buf][k1][m1] = pb1;             \
        }

        float acc[8][8];
#pragma unroll
        for (int i = 0; i < 8; i++)
#pragma unroll
            for (int j = 0; j < 8; j++) acc[i][j] = 0.f;

        LDG_TILE(0);
        STS_TILE(0);

        for (int kc = 0; kc < 6; kc++) {
            __syncthreads();
            if (kc < 5) LDG_TILE(kc + 1);
            int buf = kc & 1;
#pragma unroll
            for (int k = 0; k < 16; k++) {
                float4 a0 = *(const float4*)&As[buf][k][ty * 4];
                float4 a1 = *(const float4*)&As[buf][k][64 + ty * 4];
                float4 b0 = *(const float4*)&Bs[buf][k][tx * 4];
                float4 b1 = *(const float4*)&Bs[buf][k][64 + tx * 4];
                float ar[8] = {a0.x, a0.y, a0.z, a0.w, a1.x, a1.y, a1.z, a1.w};
                float br[8] = {b0.x, b0.y, b0.z, b0.w, b1.x, b1.y, b1.z, b1.w};
#pragma unroll
                for (int i = 0; i < 8; i++)
#pragma unroll
                    for (int j = 0; j < 8; j++) acc[i][j] += ar[i] * br[j];
            }
            if (kc < 5) STS_TILE((kc + 1) & 1);
        }
#undef LDG_TILE
#undef STS_TILE

        float x2i[8], x2j[8];
#pragma unroll
        for (int g = 0; g < 2; g++)
#pragma unroll
            for (int q = 0; q < 4; q++) {
                int ni = ni0 + g * 64 + ty * 4 + q;
                int nj = nj0 + g * 64 + tx * 4 + q;
                x2i[g * 4 + q] = (ni < NN) ? g_x2[b * NN + ni] : 0.f;
                x2j[g * 4 + q] = (nj < NN) ? g_x2[b * NN + nj] : 0.f;
            }

#pragma unroll
        for (int rg = 0; rg < 2; rg++)
#pragma unroll
            for (int r = 0; r < 4; r++) {
                int ni = ni0 + rg * 64 + ty * 4 + r;
                if (ni < NN) {
                    int ri = rg * 4 + r;
#pragma unroll
                    for (int cg = 0; cg < 2; cg++) {
                        int cb = nj0 + cg * 64 + tx * 4;
                        if (cb < NN) {
                            float4 v;
                            v.x = x2j[cg * 4 + 0] - 2.f * acc[ri][cg * 4 + 0];
                            v.y = x2j[cg * 4 + 1] - 2.f * acc[ri][cg * 4 + 1];
                            v.z = x2j[cg * 4 + 2] - 2.f * acc[ri][cg * 4 + 2];
                            v.w = x2j[cg * 4 + 3] - 2.f * acc[ri][cg * 4 + 3];
                            *(float4*)&Db[(size_t)ni * NN + cb] = v;
                        }
                    }
                }
            }

        if (bi < bj) {
#pragma unroll
            for (int cg = 0; cg < 2; cg++)
#pragma unroll
                for (int jj = 0; jj < 4; jj++) {
                    int nj = nj0 + cg * 64 + tx * 4 + jj;
                    if (nj < NN) {
                        int ci = cg * 4 + jj;
#pragma unroll
                        for (int rg = 0; rg < 2; rg++) {
                            int rb = ni0 + rg * 64 + ty * 4;
                            if (rb < NN) {
                                float4 v;
                                v.x = x2i[rg * 4 + 0] - 2.f * acc[rg * 4 + 0][ci];
                                v.y = x2i[rg * 4 + 1] - 2.f * acc[rg * 4 + 1][ci];
                                v.z = x2i[rg * 4 + 2] - 2.f * acc[rg * 4 + 2][ci];
                                v.w = x2i[rg * 4 + 3] - 2.f * acc[rg * 4 + 3][ci];
                                *(float4*)&Db[(size_t)nj * NN + rb] = v;
                            }
                        }
                    }
                }
        }
    } else {
        int q = p - 325;
        int bn = q % 25;
        int br = q / 25;
        int r0 = br * 128, n0 = bn * 128;
        const float* hb = g_h + (size_t)b * 96 * NN;

#define LDG_TILE(kc)                                                                        \
        {                                                                                   \
            int c0 = (kc) * 16 + k0, c1 = (kc) * 16 + k1;                                   \
            pa0 = *(const float4*)(g_wt + c0 * 384 + r0 + m0);                              \
            pa1 = *(const float4*)(g_wt + c1 * 384 + r0 + m1);                              \
            pb0 = (n0 + m0 < NN) ? *(const float4*)(hb + (size_t)c0 * NN + n0 + m0) : z4;   \
            pb1 = (n0 + m1 < NN) ? *(const float4*)(hb + (size_t)c1 * NN + n0 + m1) : z4;   \
        }
#define STS_TILE(buf)                                                                       \
        {                                                                                   \
            *(float4*)&As[buf][k0][m0] = pa0; *(float4*)&As[buf][k1][m1] = pa1;             \
            *(float4*)&Bs[buf][k0][m0] = pb0; *(float4*)&Bs[buf][k1][m1] = pb1;             \
        }

        float acc[8][8];
#pragma unroll
        for (int i = 0; i < 8; i++)
#pragma unroll
            for (int j = 0; j < 8; j++) acc[i][j] = 0.f;

        LDG_TILE(0);
        STS_TILE(0);

        for (int kc = 0; kc < 6; kc++) {
            __syncthreads();
            if (kc < 5) LDG_TILE(kc + 1);
            int buf = kc & 1;
#pragma unroll
            for (int k = 0; k < 16; k++) {
                float4 a0 = *(const float4*)&As[buf][k][ty * 4];
                float4 a1 = *(const float4*)&As[buf][k][64 + ty * 4];
                float4 b0 = *(const float4*)&Bs[buf][k][tx * 4];
                float4 b1 = *(const float4*)&Bs[buf][k][64 + tx * 4];
                float ar[8] = {a0.x, a0.y, a0.z, a0.w, a1.x, a1.y, a1.z, a1.w};
                float br2[8] = {b0.x, b0.y, b0.z, b0.w, b1.x, b1.y, b1.z, b1.w};
#pragma unroll
                for (int i = 0; i < 8; i++)
#pragma unroll
                    for (int j = 0; j < 8; j++) acc[i][j] += ar[i] * br2[j];
            }
            if (kc < 5) STS_TILE((kc + 1) & 1);
        }
#undef LDG_TILE
#undef STS_TILE

        float bv[8];
#pragma unroll
        for (int rg = 0; rg < 2; rg++)
#pragma unroll
            for (int r = 0; r < 4; r++) bv[rg * 4 + r] = g_ub[r0 + rg * 64 + ty * 4 + r];

#pragma unroll
        for (int cg = 0; cg < 2; cg++)
#pragma unroll
            for (int jj = 0; jj < 4; jj++) {
                int n = n0 + cg * 64 + tx * 4 + jj;
                if (n < NN) {
                    int ci = cg * 4 + jj;
                    float* dst = g_uv + ((size_t)(b * NN) + n) * 384 + r0;
#pragma unroll
                    for (int rg = 0; rg < 2; rg++) {
                        float4 v;
                        v.x = acc[rg * 4 + 0][ci] + bv[rg * 4 + 0];
                        v.y = acc[rg * 4 + 1][ci] + bv[rg * 4 + 1];
                        v.z = acc[rg * 4 + 2][ci] + bv[rg * 4 + 2];
                        v.w = acc[rg * 4 + 3][ci] + bv[rg * 4 + 3];
                        *(float4*)(dst + rg * 64 + ty * 4) = v;
                    }
                }
            }
    }
}

// ---------------- K3: top-9, MLP=4 loads + 8-wide spill-free insert groups ----------
__device__ __forceinline__ unsigned long long pack_key(float d, int id) {
    unsigned u = __float_as_uint(d);
    u ^= (u & 0x80000000u) ? 0xFFFFFFFFu : 0x80000000u;  // sortable-float map
    return ((unsigned long long)u << 32) | (unsigned)id;
}

__device__ __forceinline__ float key_to_dist(unsigned long long k) {
    unsigned u = (unsigned)(k >> 32);
    u ^= (u & 0x80000000u) ? 0x80000000u : 0xFFFFFFFFu;  // inverse map
    return __uint_as_float(u);
}

// exact u64 insert of an 8-candidate group (same machinery as R14; no big arrays)
__device__ __forceinline__ void insert_group8(
    float4 a, float4 c, int baseA, int baseB,
    unsigned long long& q9, unsigned long long& wth, float& wth_f, int lane)
{
    const unsigned FULL = 0xffffffffu;
    const unsigned long long KMAX = 0xFFFFFFFFFFFFFFFFull;
    float mn = fminf(fminf(fminf(a.x, a.y), fminf(a.z, a.w)),
                     fminf(fminf(c.x, c.y), fminf(c.z, c.w)));
    unsigned g = __ballot_sync(FULL, mn <= wth_f);
    if (!g) return;

    float dv[8] = {a.x, a.y, a.z, a.w, c.x, c.y, c.z, c.w};
    int   iv[8] = {baseA, baseA + 1, baseA + 2, baseA + 3,
                   baseB, baseB + 1, baseB + 2, baseB + 3};
#pragma unroll
    for (int qq = 0; qq < 8; qq++) {
        float d = dv[qq];
        unsigned long long k = (d <= wth_f) ? pack_key(d, iv[qq]) : KMAX;
        for (int r = 0; r < 32; r++) {
            unsigned m = __ballot_sync(FULL, k < wth);
            if (!m) break;
            int src = __ffs(m) - 1;
            unsigned long long bk = __shfl_sync(FULL, k, src);
            unsigned long long prev = __shfl_up_sync(FULL, q9, 1);
            if (lane == 0) prev = 0ull;
            q9 = (bk >= q9) ? q9 : (prev > bk ? prev : bk);
            wth = __shfl_sync(FULL, q9, 8);
            wth_f = key_to_dist(wth);
            if (lane == src) k = KMAX;
        }
    }
}

__global__ void k_topk() {
    const unsigned long long KMAX = 0xFFFFFFFFFFFFFFFFull;
    int warp = threadIdx.x >> 5;
    int lane = threadIdx.x & 31;
    int row = blockIdx.x * 8 + warp;  // b*NN + n
    const float4* Drow = (const float4*)(g_D + (size_t)row * NN);

    unsigned long long q9 = KMAX;   // lanes 0..8: sorted top-9 ascending
    unsigned long long wth = KMAX;  // q9 @ lane 8 (warp-uniform)
    float wth_f = FLT_MAX;

    const float4 m4 = make_float4(FLT_MAX, FLT_MAX, FLT_MAX, FLT_MAX);

    for (int it = 0; it < 7; it++) {    // 7*128 = 896 >= 784 float4 slots
        int sA = it * 128 + lane;
        int sB = sA + 32;
        int sC = sA + 64;
        int sD = sA + 96;
        // 4 independent loads issued before any consumption (MLP=4)
        float4 a = (sA < 784) ? __ldcs(&Drow[sA]) : m4;
        float4 c = (sB < 784) ? __ldcs(&Drow[sB]) : m4;
        float4 e = (sC < 784) ? __ldcs(&Drow[sC]) : m4;
        float4 f = (sD < 784) ? __ldcs(&Drow[sD]) : m4;

        insert_group8(a, c, sA * 4, sB * 4, q9, wth, wth_f, lane);
        insert_group8(e, f, sC * 4, sD * 4, q9, wth, wth_f, lane);
    }
    if (lane < 9) g_idx[row * 9 + lane] = (int)(q9 & 0xFFFFFFFFull);
}

// ---------------- K5a: gather + maxpool + relu -> g_g[node][192] ----------------
__global__ void k_gather() {
    int tid = threadIdx.x;
    int warp = tid >> 5, lane = tid & 31;
    int node = blockIdx.x * 8 + warp;
    int b = node / NN, n = node % NN;
    const float* uvb = g_uv + (size_t)b * NN * 384;

    int nb[9];
#pragma unroll
    for (int k = 0; k < 9; k++) nb[k] = g_idx[node * 9 + k];

#pragma unroll
    for (int s = 0; s < 6; s++) {
        int c = lane + 32 * s;
        float u = uvb[(size_t)n * 384 + c];
        float m = -FLT_MAX;
#pragma unroll
        for (int k = 0; k < 9; k++)
            m = fmaxf(m, uvb[(size_t)nb[k] * 384 + 192 + c]);
        g_g[(size_t)node * 192 + c] = fmaxf(u + m, 0.f);
    }
}

// ---------------- K5b: fc2 GEMM 96x64 tiles + avg/max epilogue ----------------
__global__ void __launch_bounds__(256) k_fc2(const float* __restrict__ fw,
                                             const float* __restrict__ fb) {
    __shared__ float Ws[32][97];
    __shared__ float gs[32][68];
    __shared__ float red_s[16][68];
    __shared__ float red_m[16][68];

    int tid = threadIdx.x;
    int tx = tid & 15, ty = tid >> 4;
    int bn = blockIdx.x;
    int b  = blockIdx.y;
    int n0 = bn * 64;
    const float* gbase = g_g + ((size_t)b * NN + n0) * 192;

    float acc[6][4] = {};

    for (int kc = 0; kc < 6; kc++) {
        __syncthreads();
        for (int i = tid; i < 96 * 32; i += 256) {
            int o = i >> 5, cl = i & 31;
            Ws[cl][o] = fw[o * 192 + kc * 32 + cl];
        }
        for (int i = tid; i < 512; i += 256) {
            int n = i >> 3, cq = i & 7;
            float4 v = *(const float4*)(gbase + (size_t)n * 192 + kc * 32 + cq * 4);
            gs[cq * 4 + 0][n] = v.x;
            gs[cq * 4 + 1][n] = v.y;
            gs[cq * 4 + 2][n] = v.z;
            gs[cq * 4 + 3][n] = v.w;
        }
        __syncthreads();
#pragma unroll
        for (int k = 0; k < 32; k++) {
            float4 gv = *(const float4*)&gs[k][tx * 4];
            float gr[4] = {gv.x, gv.y, gv.z, gv.w};
#pragma unroll
            for (int q = 0; q < 6; q++) {
                float wv = Ws[k][ty * 6 + q];
#pragma unroll
                for (int p = 0; p < 4; p++) acc[q][p] += wv * gr[p];
            }
        }
    }

    float psum[4] = {0.f, 0.f, 0.f, 0.f};
    float pmax[4] = {-FLT_MAX, -FLT_MAX, -FLT_MAX, -FLT_MAX};
#pragma unroll
    for (int q = 0; q < 6; q++) {
        int o = ty * 6 + q;
        float bias = fb[o];
        float4 v;
        float vv[4];
#pragma unroll
        for (int p = 0; p < 4; p++) {
            vv[p] = acc[q][p] + bias;
            psum[p] += vv[p];
            pmax[p] = fmaxf(pmax[p], vv[p]);
        }
        v.x = vv[0]; v.y = vv[1]; v.z = vv[2]; v.w = vv[3];
        *(float4*)&g_out[((size_t)(b * 96 + o)) * NN + n0 + tx * 4] = v;
    }
    __syncthreads();
#pragma unroll
    for (int p = 0; p < 4; p++) {
        red_s[ty][tx * 4 + p] = psum[p];
        red_m[ty][tx * 4 + p] = pmax[p];
    }
    __syncthreads();
#pragma unroll
    for (int off = 8; off > 0; off >>= 1) {
        if (ty < off) {
#pragma unroll
            for (int p = 0; p < 4; p++) {
                red_s[ty][tx * 4 + p] += red_s[ty + off][tx * 4 + p];
                red_m[ty][tx * 4 + p] = fmaxf(red_m[ty][tx * 4 + p], red_m[ty + off][tx * 4 + p]);
            }
        }
        __syncthreads();
    }
    if (ty == 0) {
#pragma unroll
        for (int p = 0; p < 4; p++) {
            g_avg[b * NN + n0 + tx * 4 + p] = red_s[0][tx * 4 + p] * (1.f / 96.f);
            g_mx[b * NN + n0 + tx * 4 + p]  = red_m[0][tx * 4 + p];
        }
    }
}

// ---------------- K6: 7x7 spatial attention + sigmoid + residual ----------------
__global__ void k_att(const float* __restrict__ sw_g, const float* __restrict__ x,
                      float* __restrict__ out) {
    __shared__ float sw[98];
    int tid = threadIdx.x;
    if (tid < 98) sw[tid] = sw_g[tid];
    __syncthreads();
    int b = blockIdx.y;
    int n = blockIdx.x * 256 + tid;
    if (n >= NN) return;
    int y = n / HH, x0 = n % HH;
    const float* avgb = g_avg + b * NN;
    const float* mxb  = g_mx + b * NN;
    float acc = 0.f;
#pragma unroll
    for (int dy = 0; dy < 7; dy++) {
        int yy = y + dy - 3;
        if ((unsigned)yy < HH) {
#pragma unroll
            for (int dx = 0; dx < 7; dx++) {
                int xx = x0 + dx - 3;
                if ((unsigned)xx < HH) {
                    int nn = yy * HH + xx;
                    acc += sw[dy * 7 + dx] * avgb[nn] + sw[49 + dy * 7 + dx] * mxb[nn];
                }
            }
        }
    }
    float att = 1.f / (1.f + expf(-acc));
    for (int o = 0; o < 96; o++) {
        size_t off = ((size_t)(b * 96 + o)) * NN + n;
        out[off] = g_out[off] * att + x[off];
    }
}

// ---------------- launch ----------------
extern "C" void kernel_launch(void* const* d_in, const int* in_sizes, int n_in,
                              void* d_out, int out_size) {
    const float* x       = (const float*)d_in[0];
    const float* fc1_w   = (const float*)d_in[1];
    const float* fc1_b   = (const float*)d_in[2];
    const float* gconv_w = (const float*)d_in[3];
    const float* gconv_b = (const float*)d_in[4];
    const float* fc2_w   = (const float*)d_in[5];
    const float* fc2_b   = (const float*)d_in[6];
    const float* sa_w    = (const float*)d_in[7];
    float* out = (float*)d_out;

    k_fc1  <<<dim3(49, 4), 256>>>(x, fc1_w, fc1_b);
    k_prep <<<144, 256>>>(gconv_w, gconv_b);
    k_gemm <<<dim3(400, 4), 256>>>();      // fused dist (325) + uv (75)
    k_topk <<<1568, 256>>>();
    k_gather<<<1568, 256>>>();
    k_fc2  <<<dim3(49, 4), 256>>>(fc2_w, fc2_b);
    k_att  <<<dim3(13, 4), 256>>>(sa_w, x, out);
}

// round 17
// speedup vs baseline: 1.2133x; 1.1996x over previous
#include <cuda_runtime.h>
#include <float.h>
#include <math.h>

#define NB 4
#define CC 96
#define NN 3136
#define KNN 9
#define CMM 192
#define HH 56

// ---------------- scratch (device globals: allocation-free) ----------------
__device__ __align__(16) float g_h[NB * CC * NN];                 // fc1 output [b][c][n]
__device__ __align__(16) float g_x2[NB * NN];                     // sum h^2 per node
__device__ __align__(16) float g_D[(size_t)NB * NN * NN];         // reduced dist (157MB)
__device__ __align__(16) float g_wt[CC * 384];                    // combined uv weight [c][r]
__device__ __align__(16) float g_ub[384];                         // combined uv bias
__device__ __align__(16) float g_uv[(size_t)NB * NN * 384];       // [b][n][0..191]=u,[192..383]=v
__device__ __align__(16) float g_g[(size_t)NB * NN * CMM];        // gathered features [node][192]
__device__ __align__(16) float g_out[NB * CC * NN];               // pre-attention out [b][o][n]
__device__ __align__(16) float g_avg[NB * NN];
__device__ __align__(16) float g_mx[NB * NN];

// ---------------- K1: fc1 (h = W x + b) and x2 ----------------
__global__ void k_fc1(const float* __restrict__ x, const float* __restrict__ w,
                      const float* __restrict__ bias) {
    __shared__ __align__(16) float Xs[96][64];
    __shared__ float Ws[32][96];
    __shared__ float S2[256];
    int b = blockIdx.y;
    int n0 = blockIdx.x * 64;
    int tid = threadIdx.x;

    for (int i = tid; i < 96 * 64; i += 256) {
        int c = i >> 6, j = i & 63;
        Xs[c][j] = x[((b * 96) + c) * NN + n0 + j];
    }
    int oz = tid >> 6;
    int j  = tid & 63;
    float s2 = 0.f;

    for (int oc = 0; oc < 3; oc++) {
        __syncthreads();
        for (int i = tid; i < 32 * 96; i += 256) {
            int oo = i / 96, c = i % 96;
            Ws[oo][c] = w[(oc * 32 + oo) * 96 + c];
        }
        __syncthreads();
        float acc[8];
#pragma unroll
        for (int q = 0; q < 8; q++) acc[q] = bias[oc * 32 + oz * 8 + q];
        for (int c = 0; c < 96; c++) {
            float xc = Xs[c][j];
#pragma unroll
            for (int q = 0; q < 8; q++) acc[q] += Ws[oz * 8 + q][c] * xc;
        }
#pragma unroll
        for (int q = 0; q < 8; q++) {
            int o = oc * 32 + oz * 8 + q;
            g_h[((b * 96) + o) * NN + n0 + j] = acc[q];
            s2 += acc[q] * acc[q];
        }
    }
    S2[tid] = s2;
    __syncthreads();
    if (oz == 0) {
        float t = S2[j] + S2[64 + j] + S2[128 + j] + S2[192 + j];
        g_x2[b * NN + n0 + j] = t;
    }
}

// ---------------- K1b: combined uv weights (transposed) + bias ----------------
__global__ void k_prep(const float* __restrict__ gw, const float* __restrict__ gb) {
    int i = blockIdx.x * 256 + threadIdx.x;
    if (i < 96 * 384) {
        int c = i / 384, r = i % 384;
        float wv = (r < 192) ? gw[r * 192 + c] - gw[r * 192 + 96 + c]
                             : gw[(r - 192) * 192 + 96 + c];
        g_wt[c * 384 + r] = wv;
    }
    if (i < 384) g_ub[i] = (i < 192) ? gb[i] : 0.f;
}

// ---------------- K2: FUSED gemm kernel: dist (p<325) + uv (p>=325) ----------------
__global__ void __launch_bounds__(256, 2) k_gemm() {
    __shared__ __align__(16) float smem_buf[8192];
    float (*As)[16][128] = (float(*)[16][128])smem_buf;
    float (*Bs)[16][128] = (float(*)[16][128])(smem_buf + 4096);

    int p = blockIdx.x;
    int b = blockIdx.y;
    int tid = threadIdx.x, tx = tid & 15, ty = tid >> 4;

    int s0 = tid, s1 = tid + 256;
    int k0 = s0 >> 5, m0 = (s0 & 31) * 4;
    int k1 = s1 >> 5, m1 = (s1 & 31) * 4;

    float4 pa0, pa1, pb0, pb1;
    const float4 z4 = make_float4(0.f, 0.f, 0.f, 0.f);

    if (p < 325) {
        int bj = (int)((sqrtf(8.0f * (float)p + 1.0f) - 1.0f) * 0.5f);
        while ((bj + 1) * (bj + 2) / 2 <= p) bj++;
        while (bj * (bj + 1) / 2 > p) bj--;
        int bi = p - bj * (bj + 1) / 2;

        int ni0 = bi * 128, nj0 = bj * 128;
        const float* hb = g_h + (size_t)b * 96 * NN;
        float* Db = g_D + (size_t)b * NN * NN;

#define LDG_TILE(kc)                                                                        \
        {                                                                                   \
            int c0 = (kc) * 16 + k0, c1 = (kc) * 16 + k1;                                   \
            pa0 = (ni0 + m0 < NN) ? *(const float4*)(hb + (size_t)c0 * NN + ni0 + m0) : z4; \
            pa1 = (ni0 + m1 < NN) ? *(const float4*)(hb + (size_t)c1 * NN + ni0 + m1) : z4; \
            pb0 = (nj0 + m0 < NN) ? *(const float4*)(hb + (size_t)c0 * NN + nj0 + m0) : z4; \
            pb1 = (nj0 + m1 < NN) ? *(const float4*)(hb + (size_t)c1 * NN + nj0 + m1) : z4; \
        }
#define STS_TILE(buf)                                                                       \
        {                                                                                   \
            *(float4*)&As[buf][k0][m0] = pa0; *(float4*)&As[buf][k1][m1] = pa1;             \
            *(float4*)&Bs[buf][k0][m0] = pb0; *(float4*)&Bs[buf][k1][m1] = pb1;             \
        }

        float acc[8][8];
#pragma unroll
        for (int i = 0; i < 8; i++)
#pragma unroll
            for (int j = 0; j < 8; j++) acc[i][j] = 0.f;

        LDG_TILE(0);
        STS_TILE(0);

        for (int kc = 0; kc < 6; kc++) {
            __syncthreads();
            if (kc < 5) LDG_TILE(kc + 1);
            int buf = kc & 1;
#pragma unroll
            for (int k = 0; k < 16; k++) {
                float4 a0 = *(const float4*)&As[buf][k][ty * 4];
                float4 a1 = *(const float4*)&As[buf][k][64 + ty * 4];
                float4 b0 = *(const float4*)&Bs[buf][k][tx * 4];
                float4 b1 = *(const float4*)&Bs[buf][k][64 + tx * 4];
                float ar[8] = {a0.x, a0.y, a0.z, a0.w, a1.x, a1.y, a1.z, a1.w};
                float br[8] = {b0.x, b0.y, b0.z, b0.w, b1.x, b1.y, b1.z, b1.w};
#pragma unroll
                for (int i = 0; i < 8; i++)
#pragma unroll
                    for (int j = 0; j < 8; j++) acc[i][j] += ar[i] * br[j];
            }
            if (kc < 5) STS_TILE((kc + 1) & 1);
        }
#undef LDG_TILE
#undef STS_TILE

        float x2i[8], x2j[8];
#pragma unroll
        for (int g = 0; g < 2; g++)
#pragma unroll
            for (int q = 0; q < 4; q++) {
                int ni = ni0 + g * 64 + ty * 4 + q;
                int nj = nj0 + g * 64 + tx * 4 + q;
                x2i[g * 4 + q] = (ni < NN) ? g_x2[b * NN + ni] : 0.f;
                x2j[g * 4 + q] = (nj < NN) ? g_x2[b * NN + nj] : 0.f;
            }

#pragma unroll
        for (int rg = 0; rg < 2; rg++)
#pragma unroll
            for (int r = 0; r < 4; r++) {
                int ni = ni0 + rg * 64 + ty * 4 + r;
                if (ni < NN) {
                    int ri = rg * 4 + r;
#pragma unroll
                    for (int cg = 0; cg < 2; cg++) {
                        int cb = nj0 + cg * 64 + tx * 4;
                        if (cb < NN) {
                            float4 v;
                            v.x = x2j[cg * 4 + 0] - 2.f * acc[ri][cg * 4 + 0];
                            v.y = x2j[cg * 4 + 1] - 2.f * acc[ri][cg * 4 + 1];
                            v.z = x2j[cg * 4 + 2] - 2.f * acc[ri][cg * 4 + 2];
                            v.w = x2j[cg * 4 + 3] - 2.f * acc[ri][cg * 4 + 3];
                            *(float4*)&Db[(size_t)ni * NN + cb] = v;
                        }
                    }
                }
            }

        if (bi < bj) {
#pragma unroll
            for (int cg = 0; cg < 2; cg++)
#pragma unroll
                for (int jj = 0; jj < 4; jj++) {
                    int nj = nj0 + cg * 64 + tx * 4 + jj;
                    if (nj < NN) {
                        int ci = cg * 4 + jj;
#pragma unroll
                        for (int rg = 0; rg < 2; rg++) {
                            int rb = ni0 + rg * 64 + ty * 4;
                            if (rb < NN) {
                                float4 v;
                                v.x = x2i[rg * 4 + 0] - 2.f * acc[rg * 4 + 0][ci];
                                v.y = x2i[rg * 4 + 1] - 2.f * acc[rg * 4 + 1][ci];
                                v.z = x2i[rg * 4 + 2] - 2.f * acc[rg * 4 + 2][ci];
                                v.w = x2i[rg * 4 + 3] - 2.f * acc[rg * 4 + 3][ci];
                                *(float4*)&Db[(size_t)nj * NN + rb] = v;
                            }
                        }
                    }
                }
        }
    } else {
        int q = p - 325;
        int bn = q % 25;
        int br = q / 25;
        int r0 = br * 128, n0 = bn * 128;
        const float* hb = g_h + (size_t)b * 96 * NN;

#define LDG_TILE(kc)                                                                        \
        {                                                                                   \
            int c0 = (kc) * 16 + k0, c1 = (kc) * 16 + k1;                                   \
            pa0 = *(const float4*)(g_wt + c0 * 384 + r0 + m0);                              \
            pa1 = *(const float4*)(g_wt + c1 * 384 + r0 + m1);                              \
            pb0 = (n0 + m0 < NN) ? *(const float4*)(hb + (size_t)c0 * NN + n0 + m0) : z4;   \
            pb1 = (n0 + m1 < NN) ? *(const float4*)(hb + (size_t)c1 * NN + n0 + m1) : z4;   \
        }
#define STS_TILE(buf)                                                                       \
        {                                                                                   \
            *(float4*)&As[buf][k0][m0] = pa0; *(float4*)&As[buf][k1][m1] = pa1;             \
            *(float4*)&Bs[buf][k0][m0] = pb0; *(float4*)&Bs[buf][k1][m1] = pb1;             \
        }

        float acc[8][8];
#pragma unroll
        for (int i = 0; i < 8; i++)
#pragma unroll
            for (int j = 0; j < 8; j++) acc[i][j] = 0.f;

        LDG_TILE(0);
        STS_TILE(0);

        for (int kc = 0; kc < 6; kc++) {
            __syncthreads();
            if (kc < 5) LDG_TILE(kc + 1);
            int buf = kc & 1;
#pragma unroll
            for (int k = 0; k < 16; k++) {
                float4 a0 = *(const float4*)&As[buf][k][ty * 4];
                float4 a1 = *(const float4*)&As[buf][k][64 + ty * 4];
                float4 b0 = *(const float4*)&Bs[buf][k][tx * 4];
                float4 b1 = *(const float4*)&Bs[buf][k][64 + tx * 4];
                float ar[8] = {a0.x, a0.y, a0.z, a0.w, a1.x, a1.y, a1.z, a1.w};
                float br2[8] = {b0.x, b0.y, b0.z, b0.w, b1.x, b1.y, b1.z, b1.w};
#pragma unroll
                for (int i = 0; i < 8; i++)
#pragma unroll
                    for (int j = 0; j < 8; j++) acc[i][j] += ar[i] * br2[j];
            }
            if (kc < 5) STS_TILE((kc + 1) & 1);
        }
#undef LDG_TILE
#undef STS_TILE

        float bv[8];
#pragma unroll
        for (int rg = 0; rg < 2; rg++)
#pragma unroll
            for (int r = 0; r < 4; r++) bv[rg * 4 + r] = g_ub[r0 + rg * 64 + ty * 4 + r];

#pragma unroll
        for (int cg = 0; cg < 2; cg++)
#pragma unroll
            for (int jj = 0; jj < 4; jj++) {
                int n = n0 + cg * 64 + tx * 4 + jj;
                if (n < NN) {
                    int ci = cg * 4 + jj;
                    float* dst = g_uv + ((size_t)(b * NN) + n) * 384 + r0;
#pragma unroll
                    for (int rg = 0; rg < 2; rg++) {
                        float4 v;
                        v.x = acc[rg * 4 + 0][ci] + bv[rg * 4 + 0];
                        v.y = acc[rg * 4 + 1][ci] + bv[rg * 4 + 1];
                        v.z = acc[rg * 4 + 2][ci] + bv[rg * 4 + 2];
                        v.w = acc[rg * 4 + 3][ci] + bv[rg * 4 + 3];
                        *(float4*)(dst + rg * 64 + ty * 4) = v;
                    }
                }
            }
    }
}

// ---------------- K3: top-9 (R14 scan, verbatim) + fused gather epilogue ------------
__device__ __forceinline__ unsigned long long pack_key(float d, int id) {
    unsigned u = __float_as_uint(d);
    u ^= (u & 0x80000000u) ? 0xFFFFFFFFu : 0x80000000u;  // sortable-float map
    return ((unsigned long long)u << 32) | (unsigned)id;
}

__device__ __forceinline__ float key_to_dist(unsigned long long k) {
    unsigned u = (unsigned)(k >> 32);
    u ^= (u & 0x80000000u) ? 0x80000000u : 0xFFFFFFFFu;  // inverse map
    return __uint_as_float(u);
}

__global__ void k_topk() {
    const unsigned FULL = 0xffffffffu;
    const unsigned long long KMAX = 0xFFFFFFFFFFFFFFFFull;
    int warp = threadIdx.x >> 5;
    int lane = threadIdx.x & 31;
    int row = blockIdx.x * 8 + warp;  // b*NN + n
    const float4* Drow = (const float4*)(g_D + (size_t)row * NN);

    unsigned long long q9 = KMAX;   // lanes 0..8: sorted top-9 ascending
    unsigned long long wth = KMAX;  // q9 @ lane 8 (warp-uniform)
    float wth_f = FLT_MAX;          // distance at threshold (warp-uniform, conservative)

    const float4 m4 = make_float4(FLT_MAX, FLT_MAX, FLT_MAX, FLT_MAX);

    for (int it = 0; it < 13; it++) {    // 13*64 = 832 >= 784 float4 slots
        int sA = it * 64 + lane;
        int sB = sA + 32;
        bool vA = sA < 784, vB = sB < 784;
        float4 a = vA ? __ldcs(&Drow[sA]) : m4;
        float4 c = vB ? __ldcs(&Drow[sB]) : m4;

        // lane-local min of 8 (no warp ops)
        float mn = fminf(fminf(fminf(a.x, a.y), fminf(a.z, a.w)),
                         fminf(fminf(c.x, c.y), fminf(c.z, c.w)));
        unsigned g = __ballot_sync(FULL, mn <= wth_f);
        if (!g) continue;

        float dv[8] = {a.x, a.y, a.z, a.w, c.x, c.y, c.z, c.w};
        int   iv[8] = {sA * 4, sA * 4 + 1, sA * 4 + 2, sA * 4 + 3,
                       sB * 4, sB * 4 + 1, sB * 4 + 2, sB * 4 + 3};
#pragma unroll
        for (int qq = 0; qq < 8; qq++) {
            float d = dv[qq];
            unsigned long long k = (d <= wth_f) ? pack_key(d, iv[qq]) : KMAX;
            for (int r = 0; r < 32; r++) {
                unsigned m = __ballot_sync(FULL, k < wth);
                if (!m) break;
                int src = __ffs(m) - 1;
                unsigned long long bk = __shfl_sync(FULL, k, src);
                unsigned long long prev = __shfl_up_sync(FULL, q9, 1);
                if (lane == 0) prev = 0ull;
                q9 = (bk >= q9) ? q9 : (prev > bk ? prev : bk);
                wth = __shfl_sync(FULL, q9, 8);
                wth_f = key_to_dist(wth);
                if (lane == src) k = KMAX;
            }
        }
    }

    // ---- fused gather epilogue: indices live in lanes 0..8 of q9 ----
    int nb[9];
#pragma unroll
    for (int k = 0; k < 9; k++)
        nb[k] = (int)(__shfl_sync(FULL, q9, k) & 0xFFFFFFFFull);

    int b = row / NN, n = row % NN;
    const float* uvb = g_uv + (size_t)b * NN * 384;

#pragma unroll
    for (int s = 0; s < 6; s++) {
        int c = lane + 32 * s;
        float u = uvb[(size_t)n * 384 + c];
        float m = -FLT_MAX;
#pragma unroll
        for (int k = 0; k < 9; k++)
            m = fmaxf(m, uvb[(size_t)nb[k] * 384 + 192 + c]);
        g_g[(size_t)row * 192 + c] = fmaxf(u + m, 0.f);
    }
}

// ---------------- K5b: fc2 GEMM 96x64 tiles + avg/max epilogue ----------------
__global__ void __launch_bounds__(256) k_fc2(const float* __restrict__ fw,
                                             const float* __restrict__ fb) {
    __shared__ float Ws[32][97];
    __shared__ float gs[32][68];
    __shared__ float red_s[16][68];
    __shared__ float red_m[16][68];

    int tid = threadIdx.x;
    int tx = tid & 15, ty = tid >> 4;
    int bn = blockIdx.x;
    int b  = blockIdx.y;
    int n0 = bn * 64;
    const float* gbase = g_g + ((size_t)b * NN + n0) * 192;

    float acc[6][4] = {};

    for (int kc = 0; kc < 6; kc++) {
        __syncthreads();
        for (int i = tid; i < 96 * 32; i += 256) {
            int o = i >> 5, cl = i & 31;
            Ws[cl][o] = fw[o * 192 + kc * 32 + cl];
        }
        for (int i = tid; i < 512; i += 256) {
            int n = i >> 3, cq = i & 7;
            float4 v = *(const float4*)(gbase + (size_t)n * 192 + kc * 32 + cq * 4);
            gs[cq * 4 + 0][n] = v.x;
            gs[cq * 4 + 1][n] = v.y;
            gs[cq * 4 + 2][n] = v.z;
            gs[cq * 4 + 3][n] = v.w;
        }
        __syncthreads();
#pragma unroll
        for (int k = 0; k < 32; k++) {
            float4 gv = *(const float4*)&gs[k][tx * 4];
            float gr[4] = {gv.x, gv.y, gv.z, gv.w};
#pragma unroll
            for (int q = 0; q < 6; q++) {
                float wv = Ws[k][ty * 6 + q];
#pragma unroll
                for (int p = 0; p < 4; p++) acc[q][p] += wv * gr[p];
            }
        }
    }

    float psum[4] = {0.f, 0.f, 0.f, 0.f};
    float pmax[4] = {-FLT_MAX, -FLT_MAX, -FLT_MAX, -FLT_MAX};
#pragma unroll
    for (int q = 0; q < 6; q++) {
        int o = ty * 6 + q;
        float bias = fb[o];
        float4 v;
        float vv[4];
#pragma unroll
        for (int p = 0; p < 4; p++) {
            vv[p] = acc[q][p] + bias;
            psum[p] += vv[p];
            pmax[p] = fmaxf(pmax[p], vv[p]);
        }
        v.x = vv[0]; v.y = vv[1]; v.z = vv[2]; v.w = vv[3];
        *(float4*)&g_out[((size_t)(b * 96 + o)) * NN + n0 + tx * 4] = v;
    }
    __syncthreads();
#pragma unroll
    for (int p = 0; p < 4; p++) {
        red_s[ty][tx * 4 + p] = psum[p];
        red_m[ty][tx * 4 + p] = pmax[p];
    }
    __syncthreads();
#pragma unroll
    for (int off = 8; off > 0; off >>= 1) {
        if (ty < off) {
#pragma unroll
            for (int p = 0; p < 4; p++) {
                red_s[ty][tx * 4 + p] += red_s[ty + off][tx * 4 + p];
                red_m[ty][tx * 4 + p] = fmaxf(red_m[ty][tx * 4 + p], red_m[ty + off][tx * 4 + p]);
            }
        }
        __syncthreads();
    }
    if (ty == 0) {
#pragma unroll
        for (int p = 0; p < 4; p++) {
            g_avg[b * NN + n0 + tx * 4 + p] = red_s[0][tx * 4 + p] * (1.f / 96.f);
            g_mx[b * NN + n0 + tx * 4 + p]  = red_m[0][tx * 4 + p];
        }
    }
}

// ---------------- K6: 7x7 spatial attention + sigmoid + residual ----------------
__global__ void k_att(const float* __restrict__ sw_g, const float* __restrict__ x,
                      float* __restrict__ out) {
    __shared__ float sw[98];
    int tid = threadIdx.x;
    if (tid < 98) sw[tid] = sw_g[tid];
    __syncthreads();
    int b = blockIdx.y;
    int n = blockIdx.x * 256 + tid;
    if (n >= NN) return;
    int y = n / HH, x0 = n % HH;
    const float* avgb = g_avg + b * NN;
    const float* mxb  = g_mx + b * NN;
    float acc = 0.f;
#pragma unroll
    for (int dy = 0; dy < 7; dy++) {
        int yy = y + dy - 3;
        if ((unsigned)yy < HH) {
#pragma unroll
            for (int dx = 0; dx < 7; dx++) {
                int xx = x0 + dx - 3;
                if ((unsigned)xx < HH) {
                    int nn = yy * HH + xx;
                    acc += sw[dy * 7 + dx] * avgb[nn] + sw[49 + dy * 7 + dx] * mxb[nn];
                }
            }
        }
    }
    float att = 1.f / (1.f + expf(-acc));
    for (int o = 0; o < 96; o++) {
        size_t off = ((size_t)(b * 96 + o)) * NN + n;
        out[off] = g_out[off] * att + x[off];
    }
}

// ---------------- launch ----------------
extern "C" void kernel_launch(void* const* d_in, const int* in_sizes, int n_in,
                              void* d_out, int out_size) {
    const float* x       = (const float*)d_in[0];
    const float* fc1_w   = (const float*)d_in[1];
    const float* fc1_b   = (const float*)d_in[2];
    const float* gconv_w = (const float*)d_in[3];
    const float* gconv_b = (const float*)d_in[4];
    const float* fc2_w   = (const float*)d_in[5];
    const float* fc2_b   = (const float*)d_in[6];
    const float* sa_w    = (const float*)d_in[7];
    float* out = (float*)d_out;

    k_fc1  <<<dim3(49, 4), 256>>>(x, fc1_w, fc1_b);
    k_prep <<<144, 256>>>(gconv_w, gconv_b);
    k_gemm <<<dim3(400, 4), 256>>>();      // fused dist (325) + uv (75)
    k_topk <<<1568, 256>>>();              // fused top-9 + gather
    k_fc2  <<<dim3(49, 4), 256>>>(fc2_w, fc2_b);
    k_att  <<<dim3(13, 4), 256>>>(sa_w, x, out);
}